// round 9
// baseline (speedup 1.0000x reference)
#include <cuda_runtime.h>
#include <cuda_fp16.h>
#include <cstdint>

#define B_  64
#define T_  256
#define C_  2048
#define HS_ 128
#define M_  (B_ * T_)

// Scratch (no cudaMalloc allowed)
__device__ __half g_k[M_ * HS_];
__device__ __half g_q[M_ * HS_];
__device__ __half g_v[M_ * HS_];
__device__ __half g_wh[3 * HS_ * C_];   // [384][2048] fp16 RNE, K-major

__device__ __forceinline__ void cpa16(void* dst_smem, const void* src_gmem) {
    unsigned d = (unsigned)__cvta_generic_to_shared(dst_smem);
    asm volatile("cp.async.cg.shared.global [%0], [%1], 16;" :: "r"(d), "l"(src_gmem));
}
#define CP_COMMIT  asm volatile("cp.async.commit_group;")
#define CP_WAIT(n) asm volatile("cp.async.wait_group %0;" :: "n"(n))

#define MMA_F16(acc, a, b0, b1)                                                 \
    asm volatile(                                                               \
        "mma.sync.aligned.m16n8k16.row.col.f32.f16.f16.f32 "                    \
        "{%0,%1,%2,%3}, {%4,%5,%6,%7}, {%8,%9}, {%0,%1,%2,%3};"                 \
        : "+f"((acc)[0]), "+f"((acc)[1]), "+f"((acc)[2]), "+f"((acc)[3])        \
        : "r"((a)[0]), "r"((a)[1]), "r"((a)[2]), "r"((a)[3]),                   \
          "r"(b0), "r"(b1))

#define LDSM_X4(r0, r1, r2, r3, addr)                                           \
    asm volatile("ldmatrix.sync.aligned.m8n8.x4.shared.b16 {%0,%1,%2,%3}, [%4];"\
        : "=r"(r0), "=r"(r1), "=r"(r2), "=r"(r3) : "r"(addr))

#define LDSM_X4_T(r0, r1, r2, r3, addr)                                         \
    asm volatile("ldmatrix.sync.aligned.m8n8.x4.trans.shared.b16 {%0,%1,%2,%3}, [%4];"\
        : "=r"(r0), "=r"(r1), "=r"(r2), "=r"(r3) : "r"(addr))

// ----------------------------------------------------------------------------
// Prep: g_wh[p*128 + n][k] = fp16_rn(W_p[k][n])
// ----------------------------------------------------------------------------
__global__ void prep_wt(const float* __restrict__ Wk, const float* __restrict__ Wq,
                        const float* __restrict__ Wv)
{
    __shared__ float t[32][33];
    const float* W = blockIdx.z == 0 ? Wk : (blockIdx.z == 1 ? Wq : Wv);
    const int k0 = blockIdx.x * 32, n0 = blockIdx.y * 32;
    const int tx = threadIdx.x & 31, ty = threadIdx.x >> 5;
    #pragma unroll
    for (int i = 0; i < 32; i += 8)
        t[ty + i][tx] = W[(size_t)(k0 + ty + i) * HS_ + n0 + tx];
    __syncthreads();
    #pragma unroll
    for (int i = 0; i < 32; i += 8)
        g_wh[((size_t)blockIdx.z * HS_ + n0 + ty + i) * C_ + k0 + tx] =
            __float2half_rn(t[tx][ty + i]);
}

// ----------------------------------------------------------------------------
// Projection GEMM (fp16 mma m16n8k16): tile M64 x N128 x K32, one projection
// per CTA. bid = m*3 + p (the 3 consumers of an x tile dispatch together).
// 768 CTAs -> fine-grained HW work queue. 256 thr, warps 2m x 4n (32x32).
// ----------------------------------------------------------------------------
#define NKT   (C_ / 32)          // 64
#define RSA   36                  // A row stride (floats)
#define ASTGF (64 * RSA)          // 9216 B per A stage
#define BSTGH (128 * 32)          // 8192 B per B stage (halves, swizzled)
#define PSMEM (3 * (ASTGF * 4 + BSTGH * 2))   // 52224 B

__global__ __launch_bounds__(256, 2) void proj_kernel(const float* __restrict__ x)
{
    extern __shared__ char smraw[];
    float*  As = (float*)smraw;                        // 3 stages
    __half* Bs = (__half*)(smraw + 3 * ASTGF * 4);     // 3 stages, swizzled
    const uint32_t Bs_u = (uint32_t)__cvta_generic_to_shared(Bs);

    const int tid  = threadIdx.x;
    const int warp = tid >> 5, lane = tid & 31;
    const int wm = warp >> 2, wn = warp & 3;           // 2m x 4n
    const int lr = lane >> 2, lc = lane & 3;
    const int p  = blockIdx.x % 3;
    const int m0 = (blockIdx.x / 3) * 64;
    const __half* Wp = g_wh + (size_t)p * HS_ * C_;

    const int brow  = wn * 32 + (lane & 15);
    const int bsel  = (brow >> 1) & 3;
    const int bln16 = lane >> 4;

    auto load_tile = [&](int s, int j) {
        float*  Ad = As + s * ASTGF;
        __half* Bd = Bs + s * BSTGH;
        const int k0 = j * 32;
        #pragma unroll
        for (int i = 0; i < 2; i++) {                  // A: 512 x 16B
            int c = tid + i * 256, r = c >> 3, q = c & 7;
            cpa16(Ad + r * RSA + q * 4, x + (size_t)(m0 + r) * C_ + k0 + q * 4);
        }
        #pragma unroll
        for (int i = 0; i < 2; i++) {                  // B: 512 x 16B, swizzled
            int c = tid + i * 256, r = c >> 2, cc = c & 3;
            cpa16(Bd + r * 32 + ((cc ^ ((r >> 1) & 3)) * 8),
                  Wp + (size_t)r * C_ + k0 + cc * 8);
        }
        CP_COMMIT;
    };

    load_tile(0, 0);
    load_tile(1, 1);

    float acc[2][4][4] = {};

    for (int j = 0; j < NKT; j++) {
        if (j < NKT - 2) { CP_WAIT(1); } else { CP_WAIT(0); }
        __syncthreads();

        const float*   Aj  = As + (j % 3) * ASTGF;
        const uint32_t Bju = Bs_u + (uint32_t)((j % 3) * BSTGH) * 2;

        #pragma unroll
        for (int ks = 0; ks < 2; ks++) {
            const int kb = ks * 16;
            unsigned a[2][4];
            #pragma unroll
            for (int mi = 0; mi < 2; mi++) {
                const int row = wm * 32 + mi * 16 + lr;
                float2 f0 = *(const float2*)(Aj + row * RSA + kb + 2 * lc);
                float2 f1 = *(const float2*)(Aj + (row + 8) * RSA + kb + 2 * lc);
                float2 f2 = *(const float2*)(Aj + row * RSA + kb + 2 * lc + 8);
                float2 f3 = *(const float2*)(Aj + (row + 8) * RSA + kb + 2 * lc + 8);
                __half2 h0 = __floats2half2_rn(f0.x, f0.y);
                __half2 h1 = __floats2half2_rn(f1.x, f1.y);
                __half2 h2 = __floats2half2_rn(f2.x, f2.y);
                __half2 h3 = __floats2half2_rn(f3.x, f3.y);
                a[mi][0] = *reinterpret_cast<unsigned*>(&h0);
                a[mi][1] = *reinterpret_cast<unsigned*>(&h1);
                a[mi][2] = *reinterpret_cast<unsigned*>(&h2);
                a[mi][3] = *reinterpret_cast<unsigned*>(&h3);
            }
            const uint32_t chnk = (uint32_t)(((2 * ks + bln16) ^ bsel) * 16);
            #pragma unroll
            for (int pr = 0; pr < 2; pr++) {
                unsigned b0, b1, b2, b3;
                LDSM_X4(b0, b1, b2, b3,
                        Bju + (uint32_t)(brow * 64 + pr * 1024) + chnk);
                MMA_F16(acc[0][2 * pr],     a[0], b0, b2);
                MMA_F16(acc[0][2 * pr + 1], a[0], b1, b3);
                MMA_F16(acc[1][2 * pr],     a[1], b0, b2);
                MMA_F16(acc[1][2 * pr + 1], a[1], b1, b3);
            }
        }

        if (j + 2 < NKT) load_tile((j + 2) % 3, j + 2);
    }

    __half* out = p == 0 ? g_k : (p == 1 ? g_q : g_v);
    #pragma unroll
    for (int mi = 0; mi < 2; mi++) {
        const int row0 = m0 + wm * 32 + mi * 16 + lr;
        #pragma unroll
        for (int ni = 0; ni < 4; ni++) {
            const int col = wn * 32 + ni * 8 + 2 * lc;
            __half2 h1 = __floats2half2_rn(acc[mi][ni][0], acc[mi][ni][1]);
            __half2 h2 = __floats2half2_rn(acc[mi][ni][2], acc[mi][ni][3]);
            *(__half2*)(out + (size_t)row0 * HS_ + col)       = h1;
            *(__half2*)(out + (size_t)(row0 + 8) * HS_ + col) = h2;
        }
    }
}

// ----------------------------------------------------------------------------
// Attention: flash-style, fp16 mma, Q double-buffered via cp.async prefetch.
// smem: sc f32[64][68] | f,l | ph h[64][72] | K h[64][136] | Q0,Q1,V h[64][136]
// = 96768 B -> 2 CTA/SM.
// ----------------------------------------------------------------------------
__global__ __launch_bounds__(256, 2) void attn_kernel(float* __restrict__ out)
{
    extern __shared__ char smr[];
    float*  sc    = (float*)smr;                   // [64][68]
    float*  f_row = sc + 64 * 68;                  // [64]
    float*  l_row = f_row + 64;                    // [64]
    __half* ph    = (__half*)(l_row + 64);         // [64][72]
    __half* kt    = ph + 64 * 72;                  // [64][136]
    __half* q0    = kt + 64 * 136;                 // [64][136]
    __half* q1    = q0 + 64 * 136;                 // [64][136]
    __half* vb    = q1 + 64 * 136;                 // [64][136]
    const uint32_t ph_u = (uint32_t)__cvta_generic_to_shared(ph);
    const uint32_t kt_u = (uint32_t)__cvta_generic_to_shared(kt);
    const uint32_t q0_u = (uint32_t)__cvta_generic_to_shared(q0);
    const uint32_t q1_u = (uint32_t)__cvta_generic_to_shared(q1);
    const uint32_t vb_u = (uint32_t)__cvta_generic_to_shared(vb);

    const int b  = blockIdx.y;
    const int bt = blockIdx.x;
    const int tid = threadIdx.x;
    const int warp = tid >> 5, lane = tid & 31;
    const int band = (warp & 3) * 16;
    const int hf = warp >> 2;
    const int lr = lane >> 2, lc = lane & 3;
    const int t0 = bt * 64;
    const float scale = rsqrtf((float)C_);

    // lane-relative ldmatrix offsets (bytes)
    const uint32_t aK  = kt_u + (uint32_t)((band + (lane & 15)) * 136 + (lane >> 4) * 8) * 2;
    const uint32_t oQ  = (uint32_t)((hf * 32 + (lane & 7) + (lane >> 4) * 8) * 136
                                    + ((lane >> 3) & 1) * 8) * 2;
    const uint32_t aP  = ph_u + (uint32_t)((band + (lane & 15)) * 72 + (lane >> 4) * 8) * 2;
    const uint32_t bV  = vb_u + (uint32_t)(((lane & 7) + ((lane >> 3) & 1) * 8) * 136
                                           + hf * 64 + (lane >> 4) * 8) * 2;

    // preamble: K and Q(0) via cp.async
    #pragma unroll
    for (int i = 0; i < 4; i++) {
        int c = tid + i * 256, r = c >> 4, q = c & 15;
        cpa16(kt + r * 136 + q * 8, g_k + (size_t)(b * T_ + t0 + r) * HS_ + q * 8);
        cpa16(q0 + r * 136 + q * 8, g_q + (size_t)(b * T_ + r) * HS_ + q * 8);
    }
    CP_COMMIT;
    CP_WAIT(0);
    __syncthreads();

    float m_r[8], l_r[8];
    float oacc[8][4] = {};
    #pragma unroll
    for (int i = 0; i < 8; i++) { m_r[i] = -INFINITY; l_r[i] = 0.f; }

    const int n_stiles = bt + 1;
    for (int st = 0; st < n_stiles; st++) {
        const int s0 = st * 64;
        __half* qn = (st & 1) ? q0 : q1;
        const uint32_t qc_u = (st & 1) ? q1_u : q0_u;

        // prefetch Q(st+1) into the other buffer
        if (st + 1 < n_stiles) {
            #pragma unroll
            for (int i = 0; i < 4; i++) {
                int c = tid + i * 256, r = c >> 4, q = c & 15;
                cpa16(qn + r * 136 + q * 8,
                      g_q + (size_t)(b * T_ + s0 + 64 + r) * HS_ + q * 8);
            }
        }
        CP_COMMIT;

        // ---- S = K Q^T ----
        float sacc[4][4] = {};
        #pragma unroll
        for (int kk = 0; kk < 8; kk++) {
            unsigned a[4];
            LDSM_X4(a[0], a[1], a[2], a[3], aK + kk * 32);
            unsigned e0, e1, e2, e3, r0, r1, r2, r3;
            LDSM_X4(e0, e1, e2, e3, qc_u + oQ + kk * 32);
            LDSM_X4(r0, r1, r2, r3, qc_u + oQ + 16 * 136 * 2 + kk * 32);
            MMA_F16(sacc[0], a, e0, e1);
            MMA_F16(sacc[1], a, e2, e3);
            MMA_F16(sacc[2], a, r0, r1);
            MMA_F16(sacc[3], a, r2, r3);
        }
        const bool diag = (st == bt);
        #pragma unroll
        for (int nt = 0; nt < 4; nt++) {
            const int row = band + lr, col = hf * 32 + nt * 8 + 2 * lc;
            const int tg = t0 + row, sg = s0 + col;
            sc[row * 68 + col]           = (!diag || sg     <= tg)     ? sacc[nt][0] * scale : -INFINITY;
            sc[row * 68 + col + 1]       = (!diag || sg + 1 <= tg)     ? sacc[nt][1] * scale : -INFINITY;
            sc[(row + 8) * 68 + col]     = (!diag || sg     <= tg + 8) ? sacc[nt][2] * scale : -INFINITY;
            sc[(row + 8) * 68 + col + 1] = (!diag || sg + 1 <= tg + 8) ? sacc[nt][3] * scale : -INFINITY;
        }
        __syncthreads();   // (1) sc full

        // V tile -> vb (sync loads; latency overlaps softmax)
        for (int i = tid; i < 1024; i += 256) {
            int r = i >> 4, c = i & 15;
            *(uint4*)(vb + r * 136 + c * 8) =
                *(const uint4*)(g_v + (size_t)(b * T_ + s0 + r) * HS_ + c * 8);
        }

        // ---- online softmax ----
        #pragma unroll
        for (int i = 0; i < 8; i++) {
            const int row = warp * 8 + i;
            float* prow = sc + row * 68;
            float s1 = prow[lane], s2 = prow[lane + 32];
            float mt = fmaxf(s1, s2);
            #pragma unroll
            for (int o = 16; o; o >>= 1) mt = fmaxf(mt, __shfl_xor_sync(0xffffffffu, mt, o));
            float mn = fmaxf(m_r[i], mt);
            float f = __expf(m_r[i] - mn);
            __half e1h = __float2half_rn(__expf(s1 - mn));
            __half e2h = __float2half_rn(__expf(s2 - mn));
            ph[row * 72 + lane]      = e1h;
            ph[row * 72 + lane + 32] = e2h;
            float sum = __half2float(e1h) + __half2float(e2h);
            #pragma unroll
            for (int o = 16; o; o >>= 1) sum += __shfl_xor_sync(0xffffffffu, sum, o);
            l_r[i] = l_r[i] * f + sum;
            m_r[i] = mn;
            if (lane == 0) f_row[row] = f;
        }
        __syncthreads();   // (2) ph + vb + f_row ready

        {
            const float f1 = f_row[band + lr], f2 = f_row[band + lr + 8];
            #pragma unroll
            for (int nt = 0; nt < 8; nt++) {
                oacc[nt][0] *= f1; oacc[nt][1] *= f1;
                oacc[nt][2] *= f2; oacc[nt][3] *= f2;
            }
        }

        // ---- O += P V ----
        #pragma unroll
        for (int kk = 0; kk < 4; kk++) {
            unsigned pm[4];
            LDSM_X4(pm[0], pm[1], pm[2], pm[3], aP + kk * 32);
            #pragma unroll
            for (int np = 0; np < 4; np++) {
                unsigned v0, v1, v2, v3;
                LDSM_X4_T(v0, v1, v2, v3,
                          bV + (uint32_t)(kk * 16 * 136 + np * 16) * 2);
                MMA_F16(oacc[np * 2],     pm, v0, v1);
                MMA_F16(oacc[np * 2 + 1], pm, v2, v3);
            }
        }
        CP_WAIT(0);        // Q(st+1) landed
        __syncthreads();   // (3) all buffers consistent for next iter
    }

    if (lane == 0) {
        #pragma unroll
        for (int i = 0; i < 8; i++) l_row[warp * 8 + i] = l_r[i];
    }
    __syncthreads();

    {
        const float inv1 = 1.f / l_row[band + lr];
        const float inv2 = 1.f / l_row[band + lr + 8];
        const size_t r1 = (size_t)(b * T_ + t0 + band + lr) * HS_;
        const size_t r2 = (size_t)(b * T_ + t0 + band + lr + 8) * HS_;
        #pragma unroll
        for (int nt = 0; nt < 8; nt++) {
            const int col = hf * 64 + nt * 8 + 2 * lc;
            *(float2*)(out + r1 + col) = make_float2(oacc[nt][0] * inv1, oacc[nt][1] * inv1);
            *(float2*)(out + r2 + col) = make_float2(oacc[nt][2] * inv2, oacc[nt][3] * inv2);
        }
    }
}

// ----------------------------------------------------------------------------
extern "C" void kernel_launch(void* const* d_in, const int* in_sizes, int n_in,
                              void* d_out, int out_size)
{
    (void)in_sizes; (void)n_in; (void)out_size;
    const float* x  = (const float*)d_in[0];
    const float* Wk = (const float*)d_in[1];
    const float* Wq = (const float*)d_in[2];
    const float* Wv = (const float*)d_in[3];

    prep_wt<<<dim3(C_ / 32, HS_ / 32, 3), 256>>>(Wk, Wq, Wv);

    cudaFuncSetAttribute(proj_kernel, cudaFuncAttributeMaxDynamicSharedMemorySize, PSMEM);
    proj_kernel<<<(M_ / 64) * 3, 256, PSMEM>>>(x);

    const int asmem = 64 * 68 * 4 + 128 * 4 + 64 * 72 * 2 + 4 * 64 * 136 * 2;  // 96768
    cudaFuncSetAttribute(attn_kernel, cudaFuncAttributeMaxDynamicSharedMemorySize, asmem);
    attn_kernel<<<dim3(4, 64), 256, asmem>>>((float*)d_out);
}

// round 10
// speedup vs baseline: 1.3648x; 1.3648x over previous
#include <cuda_runtime.h>
#include <cuda_fp16.h>
#include <cstdint>

#define B_  64
#define T_  256
#define C_  2048
#define HS_ 128
#define M_  (B_ * T_)

// Scratch (no cudaMalloc allowed)
__device__ __half g_k[M_ * HS_];
__device__ __half g_q[M_ * HS_];
__device__ __half g_v[M_ * HS_];
__device__ __half g_wh[3 * HS_ * C_];   // [384][2048] fp16 RNE, K-major

__device__ __forceinline__ void cpa16(void* dst_smem, const void* src_gmem) {
    unsigned d = (unsigned)__cvta_generic_to_shared(dst_smem);
    asm volatile("cp.async.cg.shared.global [%0], [%1], 16;" :: "r"(d), "l"(src_gmem));
}
#define CP_COMMIT  asm volatile("cp.async.commit_group;")
#define CP_WAIT(n) asm volatile("cp.async.wait_group %0;" :: "n"(n))

#define MMA_F16(acc, a, b0, b1)                                                 \
    asm volatile(                                                               \
        "mma.sync.aligned.m16n8k16.row.col.f32.f16.f16.f32 "                    \
        "{%0,%1,%2,%3}, {%4,%5,%6,%7}, {%8,%9}, {%0,%1,%2,%3};"                 \
        : "+f"((acc)[0]), "+f"((acc)[1]), "+f"((acc)[2]), "+f"((acc)[3])        \
        : "r"((a)[0]), "r"((a)[1]), "r"((a)[2]), "r"((a)[3]),                   \
          "r"(b0), "r"(b1))

#define LDSM_X4(r0, r1, r2, r3, addr)                                           \
    asm volatile("ldmatrix.sync.aligned.m8n8.x4.shared.b16 {%0,%1,%2,%3}, [%4];"\
        : "=r"(r0), "=r"(r1), "=r"(r2), "=r"(r3) : "r"(addr))

#define LDSM_X4_T(r0, r1, r2, r3, addr)                                         \
    asm volatile("ldmatrix.sync.aligned.m8n8.x4.trans.shared.b16 {%0,%1,%2,%3}, [%4];"\
        : "=r"(r0), "=r"(r1), "=r"(r2), "=r"(r3) : "r"(addr))

// ----------------------------------------------------------------------------
// Prep: g_wh[p*128 + n][k] = fp16_rn(W_p[k][n])
// ----------------------------------------------------------------------------
__global__ void prep_wt(const float* __restrict__ Wk, const float* __restrict__ Wq,
                        const float* __restrict__ Wv)
{
    __shared__ float t[32][33];
    const float* W = blockIdx.z == 0 ? Wk : (blockIdx.z == 1 ? Wq : Wv);
    const int k0 = blockIdx.x * 32, n0 = blockIdx.y * 32;
    const int tx = threadIdx.x & 31, ty = threadIdx.x >> 5;
    #pragma unroll
    for (int i = 0; i < 32; i += 8)
        t[ty + i][tx] = W[(size_t)(k0 + ty + i) * HS_ + n0 + tx];
    __syncthreads();
    #pragma unroll
    for (int i = 0; i < 32; i += 8)
        g_wh[((size_t)blockIdx.z * HS_ + n0 + ty + i) * C_ + k0 + tx] =
            __float2half_rn(t[tx][ty + i]);
}

// ----------------------------------------------------------------------------
// Fused projection GEMM (fp16 mma m16n8k16): [16384,2048] @ [2048,384].
// M-tile 64 x N 384 (R8 config, best measured). Grid 256, 2 CTA/SM.
// 256 threads, warp grid 2m x 4n, warp tile 32 x 96. 3-stage cp.async.
// B unpadded (64 B rows), XOR swizzle chunk c -> c ^ ((row>>1)&3).
// ----------------------------------------------------------------------------
#define NF    384
#define NKT   (C_ / 32)          // 64
#define RSA   36                  // A row stride (floats)
#define ASTGF (64 * RSA)          // 9216 B per A stage
#define BSTGH (NF * 32)           // 24576 B per B stage
#define PSMEM (3 * (ASTGF * 4 + BSTGH * 2))   // 101376 B

__global__ __launch_bounds__(256, 2) void proj_kernel(const float* __restrict__ x)
{
    extern __shared__ char smraw[];
    float*  As = (float*)smraw;                        // 3 stages
    __half* Bs = (__half*)(smraw + 3 * ASTGF * 4);     // 3 stages, swizzled
    const uint32_t Bs_u = (uint32_t)__cvta_generic_to_shared(Bs);

    const int tid  = threadIdx.x;
    const int warp = tid >> 5, lane = tid & 31;
    const int wm = warp >> 2, wn = warp & 3;           // 2m x 4n
    const int lr = lane >> 2, lc = lane & 3;
    const int m0 = blockIdx.x * 64;

    const int brow  = wn * 96 + (lane & 15);
    const int bsel  = (brow >> 1) & 3;
    const int bln16 = lane >> 4;

    auto load_tile = [&](int s, int j) {
        float*  Ad = As + s * ASTGF;
        __half* Bd = Bs + s * BSTGH;
        const int k0 = j * 32;
        #pragma unroll
        for (int i = 0; i < 2; i++) {                  // A: 512 x 16B
            int c = tid + i * 256, r = c >> 3, q = c & 7;
            cpa16(Ad + r * RSA + q * 4, x + (size_t)(m0 + r) * C_ + k0 + q * 4);
        }
        #pragma unroll
        for (int i = 0; i < 6; i++) {                  // B: 1536 x 16B, swizzled
            int c = tid + i * 256, r = c >> 2, cc = c & 3;
            cpa16(Bd + r * 32 + ((cc ^ ((r >> 1) & 3)) * 8),
                  g_wh + (size_t)r * C_ + k0 + cc * 8);
        }
        CP_COMMIT;
    };

    load_tile(0, 0);
    load_tile(1, 1);

    float acc[2][12][4] = {};

    for (int j = 0; j < NKT; j++) {
        if (j < NKT - 1) { CP_WAIT(1); } else { CP_WAIT(0); }
        __syncthreads();

        // issue next-next tile loads first — they overlap this tile's MMAs
        if (j + 2 < NKT) load_tile((j + 2) % 3, j + 2);

        const float*   Aj  = As + (j % 3) * ASTGF;
        const uint32_t Bju = Bs_u + (uint32_t)((j % 3) * BSTGH) * 2;

        #pragma unroll
        for (int ks = 0; ks < 2; ks++) {
            const int kb = ks * 16;
            unsigned a[2][4];
            #pragma unroll
            for (int mi = 0; mi < 2; mi++) {
                const int row = wm * 32 + mi * 16 + lr;
                float2 f0 = *(const float2*)(Aj + row * RSA + kb + 2 * lc);
                float2 f1 = *(const float2*)(Aj + (row + 8) * RSA + kb + 2 * lc);
                float2 f2 = *(const float2*)(Aj + row * RSA + kb + 2 * lc + 8);
                float2 f3 = *(const float2*)(Aj + (row + 8) * RSA + kb + 2 * lc + 8);
                __half2 h0 = __floats2half2_rn(f0.x, f0.y);
                __half2 h1 = __floats2half2_rn(f1.x, f1.y);
                __half2 h2 = __floats2half2_rn(f2.x, f2.y);
                __half2 h3 = __floats2half2_rn(f3.x, f3.y);
                a[mi][0] = *reinterpret_cast<unsigned*>(&h0);
                a[mi][1] = *reinterpret_cast<unsigned*>(&h1);
                a[mi][2] = *reinterpret_cast<unsigned*>(&h2);
                a[mi][3] = *reinterpret_cast<unsigned*>(&h3);
            }
            const uint32_t chnk = (uint32_t)(((2 * ks + bln16) ^ bsel) * 16);
            #pragma unroll
            for (int pr = 0; pr < 6; pr++) {
                unsigned b0, b1, b2, b3;
                LDSM_X4(b0, b1, b2, b3,
                        Bju + (uint32_t)(brow * 64 + pr * 1024) + chnk);
                MMA_F16(acc[0][2 * pr],     a[0], b0, b2);
                MMA_F16(acc[0][2 * pr + 1], a[0], b1, b3);
                MMA_F16(acc[1][2 * pr],     a[1], b0, b2);
                MMA_F16(acc[1][2 * pr + 1], a[1], b1, b3);
            }
        }
    }

    // epilogue: fp16 outputs split across K/Q/V
    __half* const outp[3] = { g_k, g_q, g_v };
    #pragma unroll
    for (int mi = 0; mi < 2; mi++) {
        const int row0 = m0 + wm * 32 + mi * 16 + lr;
        #pragma unroll
        for (int ni = 0; ni < 12; ni++) {
            const int gcol = wn * 96 + ni * 8;
            __half* o = outp[gcol >> 7];
            const int col = (gcol & 127) + 2 * lc;
            __half2 h1 = __floats2half2_rn(acc[mi][ni][0], acc[mi][ni][1]);
            __half2 h2 = __floats2half2_rn(acc[mi][ni][2], acc[mi][ni][3]);
            *(__half2*)(o + (size_t)row0 * HS_ + col)       = h1;
            *(__half2*)(o + (size_t)(row0 + 8) * HS_ + col) = h2;
        }
    }
}

// ----------------------------------------------------------------------------
// Attention (R9 version): flash-style, fp16 mma, Q double-buffered cp.async.
// smem = 96768 B -> 2 CTA/SM.
// ----------------------------------------------------------------------------
__global__ __launch_bounds__(256, 2) void attn_kernel(float* __restrict__ out)
{
    extern __shared__ char smr[];
    float*  sc    = (float*)smr;                   // [64][68]
    float*  f_row = sc + 64 * 68;                  // [64]
    float*  l_row = f_row + 64;                    // [64]
    __half* ph    = (__half*)(l_row + 64);         // [64][72]
    __half* kt    = ph + 64 * 72;                  // [64][136]
    __half* q0    = kt + 64 * 136;                 // [64][136]
    __half* q1    = q0 + 64 * 136;                 // [64][136]
    __half* vb    = q1 + 64 * 136;                 // [64][136]
    const uint32_t ph_u = (uint32_t)__cvta_generic_to_shared(ph);
    const uint32_t kt_u = (uint32_t)__cvta_generic_to_shared(kt);
    const uint32_t q0_u = (uint32_t)__cvta_generic_to_shared(q0);
    const uint32_t q1_u = (uint32_t)__cvta_generic_to_shared(q1);
    const uint32_t vb_u = (uint32_t)__cvta_generic_to_shared(vb);

    const int b  = blockIdx.y;
    const int bt = blockIdx.x;
    const int tid = threadIdx.x;
    const int warp = tid >> 5, lane = tid & 31;
    const int band = (warp & 3) * 16;
    const int hf = warp >> 2;
    const int lr = lane >> 2, lc = lane & 3;
    const int t0 = bt * 64;
    const float scale = rsqrtf((float)C_);

    const uint32_t aK  = kt_u + (uint32_t)((band + (lane & 15)) * 136 + (lane >> 4) * 8) * 2;
    const uint32_t oQ  = (uint32_t)((hf * 32 + (lane & 7) + (lane >> 4) * 8) * 136
                                    + ((lane >> 3) & 1) * 8) * 2;
    const uint32_t aP  = ph_u + (uint32_t)((band + (lane & 15)) * 72 + (lane >> 4) * 8) * 2;
    const uint32_t bV  = vb_u + (uint32_t)(((lane & 7) + ((lane >> 3) & 1) * 8) * 136
                                           + hf * 64 + (lane >> 4) * 8) * 2;

    #pragma unroll
    for (int i = 0; i < 4; i++) {
        int c = tid + i * 256, r = c >> 4, q = c & 15;
        cpa16(kt + r * 136 + q * 8, g_k + (size_t)(b * T_ + t0 + r) * HS_ + q * 8);
        cpa16(q0 + r * 136 + q * 8, g_q + (size_t)(b * T_ + r) * HS_ + q * 8);
    }
    CP_COMMIT;
    CP_WAIT(0);
    __syncthreads();

    float m_r[8], l_r[8];
    float oacc[8][4] = {};
    #pragma unroll
    for (int i = 0; i < 8; i++) { m_r[i] = -INFINITY; l_r[i] = 0.f; }

    const int n_stiles = bt + 1;
    for (int st = 0; st < n_stiles; st++) {
        const int s0 = st * 64;
        __half* qn = (st & 1) ? q0 : q1;
        const uint32_t qc_u = (st & 1) ? q1_u : q0_u;

        if (st + 1 < n_stiles) {
            #pragma unroll
            for (int i = 0; i < 4; i++) {
                int c = tid + i * 256, r = c >> 4, q = c & 15;
                cpa16(qn + r * 136 + q * 8,
                      g_q + (size_t)(b * T_ + s0 + 64 + r) * HS_ + q * 8);
            }
        }
        CP_COMMIT;

        float sacc[4][4] = {};
        #pragma unroll
        for (int kk = 0; kk < 8; kk++) {
            unsigned a[4];
            LDSM_X4(a[0], a[1], a[2], a[3], aK + kk * 32);
            unsigned e0, e1, e2, e3, r0, r1, r2, r3;
            LDSM_X4(e0, e1, e2, e3, qc_u + oQ + kk * 32);
            LDSM_X4(r0, r1, r2, r3, qc_u + oQ + 16 * 136 * 2 + kk * 32);
            MMA_F16(sacc[0], a, e0, e1);
            MMA_F16(sacc[1], a, e2, e3);
            MMA_F16(sacc[2], a, r0, r1);
            MMA_F16(sacc[3], a, r2, r3);
        }
        const bool diag = (st == bt);
        #pragma unroll
        for (int nt = 0; nt < 4; nt++) {
            const int row = band + lr, col = hf * 32 + nt * 8 + 2 * lc;
            const int tg = t0 + row, sg = s0 + col;
            sc[row * 68 + col]           = (!diag || sg     <= tg)     ? sacc[nt][0] * scale : -INFINITY;
            sc[row * 68 + col + 1]       = (!diag || sg + 1 <= tg)     ? sacc[nt][1] * scale : -INFINITY;
            sc[(row + 8) * 68 + col]     = (!diag || sg     <= tg + 8) ? sacc[nt][2] * scale : -INFINITY;
            sc[(row + 8) * 68 + col + 1] = (!diag || sg + 1 <= tg + 8) ? sacc[nt][3] * scale : -INFINITY;
        }
        __syncthreads();

        for (int i = tid; i < 1024; i += 256) {
            int r = i >> 4, c = i & 15;
            *(uint4*)(vb + r * 136 + c * 8) =
                *(const uint4*)(g_v + (size_t)(b * T_ + s0 + r) * HS_ + c * 8);
        }

        #pragma unroll
        for (int i = 0; i < 8; i++) {
            const int row = warp * 8 + i;
            float* prow = sc + row * 68;
            float s1 = prow[lane], s2 = prow[lane + 32];
            float mt = fmaxf(s1, s2);
            #pragma unroll
            for (int o = 16; o; o >>= 1) mt = fmaxf(mt, __shfl_xor_sync(0xffffffffu, mt, o));
            float mn = fmaxf(m_r[i], mt);
            float f = __expf(m_r[i] - mn);
            __half e1h = __float2half_rn(__expf(s1 - mn));
            __half e2h = __float2half_rn(__expf(s2 - mn));
            ph[row * 72 + lane]      = e1h;
            ph[row * 72 + lane + 32] = e2h;
            float sum = __half2float(e1h) + __half2float(e2h);
            #pragma unroll
            for (int o = 16; o; o >>= 1) sum += __shfl_xor_sync(0xffffffffu, sum, o);
            l_r[i] = l_r[i] * f + sum;
            m_r[i] = mn;
            if (lane == 0) f_row[row] = f;
        }
        __syncthreads();

        {
            const float f1 = f_row[band + lr], f2 = f_row[band + lr + 8];
            #pragma unroll
            for (int nt = 0; nt < 8; nt++) {
                oacc[nt][0] *= f1; oacc[nt][1] *= f1;
                oacc[nt][2] *= f2; oacc[nt][3] *= f2;
            }
        }

        #pragma unroll
        for (int kk = 0; kk < 4; kk++) {
            unsigned pm[4];
            LDSM_X4(pm[0], pm[1], pm[2], pm[3], aP + kk * 32);
            #pragma unroll
            for (int np = 0; np < 4; np++) {
                unsigned v0, v1, v2, v3;
                LDSM_X4_T(v0, v1, v2, v3,
                          bV + (uint32_t)(kk * 16 * 136 + np * 16) * 2);
                MMA_F16(oacc[np * 2],     pm, v0, v1);
                MMA_F16(oacc[np * 2 + 1], pm, v2, v3);
            }
        }
        CP_WAIT(0);
        __syncthreads();
    }

    if (lane == 0) {
        #pragma unroll
        for (int i = 0; i < 8; i++) l_row[warp * 8 + i] = l_r[i];
    }
    __syncthreads();

    {
        const float inv1 = 1.f / l_row[band + lr];
        const float inv2 = 1.f / l_row[band + lr + 8];
        const size_t r1 = (size_t)(b * T_ + t0 + band + lr) * HS_;
        const size_t r2 = (size_t)(b * T_ + t0 + band + lr + 8) * HS_;
        #pragma unroll
        for (int nt = 0; nt < 8; nt++) {
            const int col = hf * 64 + nt * 8 + 2 * lc;
            *(float2*)(out + r1 + col) = make_float2(oacc[nt][0] * inv1, oacc[nt][1] * inv1);
            *(float2*)(out + r2 + col) = make_float2(oacc[nt][2] * inv2, oacc[nt][3] * inv2);
        }
    }
}

// ----------------------------------------------------------------------------
extern "C" void kernel_launch(void* const* d_in, const int* in_sizes, int n_in,
                              void* d_out, int out_size)
{
    (void)in_sizes; (void)n_in; (void)out_size;
    const float* x  = (const float*)d_in[0];
    const float* Wk = (const float*)d_in[1];
    const float* Wq = (const float*)d_in[2];
    const float* Wv = (const float*)d_in[3];

    prep_wt<<<dim3(C_ / 32, HS_ / 32, 3), 256>>>(Wk, Wq, Wv);

    cudaFuncSetAttribute(proj_kernel, cudaFuncAttributeMaxDynamicSharedMemorySize, PSMEM);
    proj_kernel<<<M_ / 64, 256, PSMEM>>>(x);

    const int asmem = 64 * 68 * 4 + 128 * 4 + 64 * 72 * 2 + 4 * 64 * 136 * 2;  // 96768
    cudaFuncSetAttribute(attn_kernel, cudaFuncAttributeMaxDynamicSharedMemorySize, asmem);
    attn_kernel<<<dim3(4, 64), 256, asmem>>>((float*)d_out);
}